// round 15
// baseline (speedup 1.0000x reference)
#include <cuda_runtime.h>
#include <math.h>

#define NV 3
#define NA 4
#define NN 50000
#define NC 128
#define NVA (NV * NA)

// Scratch; g_s zeroed each launch via memsetAsync.
__device__ __align__(16) float g_s[NVA * NC];
__device__ __align__(16) float g_u[NVA * NC];
__device__ float g_t[NVA];

// Shared chunking between pass 1 and pass 2 so pass 2 can harvest pass 1's
// L2 residue (L2 is NOT flushed across launches; only L1 is).
#define SCHUNKS 98
#define SROWS   ((NN + SCHUNKS - 1) / SCHUNKS)   // 511

// -----------------------------------------------------------------------------
// Kernel 1: column sums over the node dimension. (R13 exact: 50us, 78.5% DRAM)
// Single-wave grid (12, 98) = 1176 blocks. block = 256.
// -----------------------------------------------------------------------------
__global__ __launch_bounds__(256) void col_sum_kernel(const float* __restrict__ x) {
    const int va = blockIdx.x;
    const int n0 = blockIdx.y * SROWS;
    const int n1 = min(n0 + SROWS, NN);

    const int lane = threadIdx.x & 31;
    const int w    = threadIdx.x >> 5;

    const float4* __restrict__ xb =
        reinterpret_cast<const float4*>(x) + (size_t)va * NN * 32;

    float4 acc = make_float4(0.f, 0.f, 0.f, 0.f);
    #pragma unroll 8
    for (int n = n0 + w; n < n1; n += 8) {
        float4 val = xb[(size_t)n * 32 + lane];
        acc.x += val.x; acc.y += val.y; acc.z += val.z; acc.w += val.w;
    }

    __shared__ float4 sm[256];
    sm[threadIdx.x] = acc;
    __syncthreads();

    if (threadIdx.x < 32) {
        float4 tot = sm[threadIdx.x];
        #pragma unroll
        for (int g = 1; g < 8; g++) {
            float4 val = sm[g * 32 + threadIdx.x];
            tot.x += val.x; tot.y += val.y; tot.z += val.z; tot.w += val.w;
        }
        float* dst = g_s + va * NC + threadIdx.x * 4;
        atomicAdd(dst + 0, tot.x);
        atomicAdd(dst + 1, tot.y);
        atomicAdd(dst + 2, tot.z);
        atomicAdd(dst + 3, tot.w);
    }
}

// -----------------------------------------------------------------------------
// Kernel 2 (tiny): u[v,a,:] = (s/N) @ W[v],  t[v,a] = (s/N) . b[v]  (R13 exact)
// -----------------------------------------------------------------------------
__global__ __launch_bounds__(128) void prep_kernel(const float* __restrict__ Wm,
                                                   const float* __restrict__ b) {
    const int va = blockIdx.x;
    const int q  = blockIdx.y;
    const int v  = va >> 2;
    const int cl = threadIdx.x & 31;
    const int dg = threadIdx.x >> 5;
    const int c  = q * 32 + cl;

    __shared__ float sh_s[NC];
    __shared__ float part[4][32];

    if (threadIdx.x < NC)
        sh_s[threadIdx.x] = g_s[va * NC + threadIdx.x] * (1.0f / (float)NN);
    __syncthreads();

    const float* __restrict__ Wv = Wm + (size_t)v * NC * NC;
    float acc = 0.f;
    #pragma unroll 8
    for (int d = dg * 32; d < dg * 32 + 32; ++d)
        acc += sh_s[d] * __ldg(&Wv[d * NC + c]);
    part[dg][cl] = acc;
    __syncthreads();

    if (dg == 0)
        g_u[va * NC + c] = (part[0][cl] + part[1][cl]) + (part[2][cl] + part[3][cl]);

    if (q == 0 && dg == 1) {
        const float* __restrict__ bv = b + v * NC;
        float tb = 0.f;
        #pragma unroll
        for (int d = cl; d < NC; d += 32) tb += sh_s[d] * bv[d];
        #pragma unroll
        for (int o = 16; o; o >>= 1) tb += __shfl_xor_sync(0xFFFFFFFFu, tb, o);
        if (cl == 0) g_t[va] = tb;
    }
}

// -----------------------------------------------------------------------------
// Kernel 3: scores -> tanh -> softmax over views -> combine.
// Same math/ILP as the 119.3us version (2 nodes per warp-iteration), but the
// iteration order mirrors pass-1's chunking and walks each chunk TAIL-FIRST
// (MRU-first) to harvest the L2 residue pass 1 left behind. Misses evict the
// chunk head, which is read last and would have been evicted anyway.
// grid = (2*SCHUNKS, NA) = (196, 4); block = 256 (8 warps).
// Warp j of chunk c handles descending node pairs (n, n-16), stride 32.
// -----------------------------------------------------------------------------
__global__ __launch_bounds__(256) void combine_kernel(const float* __restrict__ x,
                                                      float* __restrict__ out) {
    const int a    = blockIdx.y;
    const int c    = blockIdx.x >> 1;
    const int hb   = blockIdx.x & 1;
    const int lane = threadIdx.x & 31;
    const int warp = threadIdx.x >> 5;
    const int j    = hb * 8 + warp;            // 0..15 warps per chunk

    const float4* ub = reinterpret_cast<const float4*>(g_u);
    const float4 u0 = ub[(size_t)(0 * NA + a) * 32 + lane];
    const float4 u1 = ub[(size_t)(1 * NA + a) * 32 + lane];
    const float4 u2 = ub[(size_t)(2 * NA + a) * 32 + lane];
    const float t0 = g_t[0 * NA + a];
    const float t1 = g_t[1 * NA + a];
    const float t2 = g_t[2 * NA + a];

    const size_t vstride = (size_t)NA * NN * 32;   // float4 units per view
    const float4* __restrict__ xb =
        reinterpret_cast<const float4*>(x) + (size_t)a * NN * 32;
    float4* __restrict__ ob =
        reinterpret_cast<float4*>(out) + (size_t)a * NN * 32;

    const int n0 = c * SROWS;
    const int n1 = min(n0 + SROWS, NN);

    int na = n1 - 1 - j;
    // Paired iterations: nodes (na, na-16), descending, stride 32.
    for (; na - 16 >= n0; na -= 32) {
        const int nb = na - 16;
        const size_t ba = (size_t)na * 32 + lane;
        const size_t bb = (size_t)nb * 32 + lane;

        const float4 xa0 = xb[ba];
        const float4 xb0 = xb[bb];
        const float4 xa1 = xb[ba + vstride];
        const float4 xb1 = xb[bb + vstride];
        const float4 xa2 = xb[ba + 2 * vstride];
        const float4 xb2 = xb[bb + 2 * vstride];

        float pa0 = xa0.x * u0.x + xa0.y * u0.y + xa0.z * u0.z + xa0.w * u0.w;
        float pa1 = xa1.x * u1.x + xa1.y * u1.y + xa1.z * u1.z + xa1.w * u1.w;
        float pa2 = xa2.x * u2.x + xa2.y * u2.y + xa2.z * u2.z + xa2.w * u2.w;
        float pb0 = xb0.x * u0.x + xb0.y * u0.y + xb0.z * u0.z + xb0.w * u0.w;
        float pb1 = xb1.x * u1.x + xb1.y * u1.y + xb1.z * u1.z + xb1.w * u1.w;
        float pb2 = xb2.x * u2.x + xb2.y * u2.y + xb2.z * u2.z + xb2.w * u2.w;

        #pragma unroll
        for (int o = 16; o; o >>= 1) {
            pa0 += __shfl_xor_sync(0xFFFFFFFFu, pa0, o);
            pb0 += __shfl_xor_sync(0xFFFFFFFFu, pb0, o);
            pa1 += __shfl_xor_sync(0xFFFFFFFFu, pa1, o);
            pb1 += __shfl_xor_sync(0xFFFFFFFFu, pb1, o);
            pa2 += __shfl_xor_sync(0xFFFFFFFFu, pa2, o);
            pb2 += __shfl_xor_sync(0xFFFFFFFFu, pb2, o);
        }
        pa0 += t0; pa1 += t1; pa2 += t2;
        pb0 += t0; pb1 += t1; pb2 += t2;

        const float ea0 = __expf(__fdividef(2.f, 1.f + __expf(-2.f * pa0)) - 1.f);
        const float eb0 = __expf(__fdividef(2.f, 1.f + __expf(-2.f * pb0)) - 1.f);
        const float ea1 = __expf(__fdividef(2.f, 1.f + __expf(-2.f * pa1)) - 1.f);
        const float eb1 = __expf(__fdividef(2.f, 1.f + __expf(-2.f * pb1)) - 1.f);
        const float ea2 = __expf(__fdividef(2.f, 1.f + __expf(-2.f * pa2)) - 1.f);
        const float eb2 = __expf(__fdividef(2.f, 1.f + __expf(-2.f * pb2)) - 1.f);

        const float inva = __fdividef(1.f, ea0 + ea1 + ea2);
        const float invb = __fdividef(1.f, eb0 + eb1 + eb2);
        const float wa0 = ea0 * inva, wa1 = ea1 * inva, wa2 = ea2 * inva;
        const float wb0 = eb0 * invb, wb1 = eb1 * invb, wb2 = eb2 * invb;

        float4 oa, obv;
        oa.x = wa0 * xa0.x + wa1 * xa1.x + wa2 * xa2.x;
        oa.y = wa0 * xa0.y + wa1 * xa1.y + wa2 * xa2.y;
        oa.z = wa0 * xa0.z + wa1 * xa1.z + wa2 * xa2.z;
        oa.w = wa0 * xa0.w + wa1 * xa1.w + wa2 * xa2.w;
        obv.x = wb0 * xb0.x + wb1 * xb1.x + wb2 * xb2.x;
        obv.y = wb0 * xb0.y + wb1 * xb1.y + wb2 * xb2.y;
        obv.z = wb0 * xb0.z + wb1 * xb1.z + wb2 * xb2.z;
        obv.w = wb0 * xb0.w + wb1 * xb1.w + wb2 * xb2.w;
        __stcs(&ob[ba], oa);
        __stcs(&ob[bb], obv);
    }

    // Tail: single leftover node for this warp (na >= n0 but na-16 < n0).
    if (na >= n0) {
        const size_t ba = (size_t)na * 32 + lane;
        const float4 xa0 = xb[ba];
        const float4 xa1 = xb[ba + vstride];
        const float4 xa2 = xb[ba + 2 * vstride];

        float pa0 = xa0.x * u0.x + xa0.y * u0.y + xa0.z * u0.z + xa0.w * u0.w;
        float pa1 = xa1.x * u1.x + xa1.y * u1.y + xa1.z * u1.z + xa1.w * u1.w;
        float pa2 = xa2.x * u2.x + xa2.y * u2.y + xa2.z * u2.z + xa2.w * u2.w;

        #pragma unroll
        for (int o = 16; o; o >>= 1) {
            pa0 += __shfl_xor_sync(0xFFFFFFFFu, pa0, o);
            pa1 += __shfl_xor_sync(0xFFFFFFFFu, pa1, o);
            pa2 += __shfl_xor_sync(0xFFFFFFFFu, pa2, o);
        }
        pa0 += t0; pa1 += t1; pa2 += t2;

        const float ea0 = __expf(__fdividef(2.f, 1.f + __expf(-2.f * pa0)) - 1.f);
        const float ea1 = __expf(__fdividef(2.f, 1.f + __expf(-2.f * pa1)) - 1.f);
        const float ea2 = __expf(__fdividef(2.f, 1.f + __expf(-2.f * pa2)) - 1.f);
        const float inva = __fdividef(1.f, ea0 + ea1 + ea2);
        const float wa0 = ea0 * inva, wa1 = ea1 * inva, wa2 = ea2 * inva;

        float4 oa;
        oa.x = wa0 * xa0.x + wa1 * xa1.x + wa2 * xa2.x;
        oa.y = wa0 * xa0.y + wa1 * xa1.y + wa2 * xa2.y;
        oa.z = wa0 * xa0.z + wa1 * xa1.z + wa2 * xa2.z;
        oa.w = wa0 * xa0.w + wa1 * xa1.w + wa2 * xa2.w;
        __stcs(&ob[ba], oa);
    }
}

// -----------------------------------------------------------------------------
extern "C" void kernel_launch(void* const* d_in, const int* in_sizes, int n_in,
                              void* d_out, int out_size) {
    const float* x  = (const float*)d_in[0];   // [V,A,N,C]
    const float* Wm = (const float*)d_in[1];   // [V,C,C]
    const float* b  = (const float*)d_in[2];   // [V,C]
    float* out = (float*)d_out;                // [A,N,C]
    (void)in_sizes; (void)n_in; (void)out_size;

    void* p = nullptr;
    cudaGetSymbolAddress(&p, g_s);
    cudaMemsetAsync(p, 0, NVA * NC * sizeof(float));

    col_sum_kernel<<<dim3(NVA, SCHUNKS), 256>>>(x);
    prep_kernel<<<dim3(NVA, 4), 128>>>(Wm, b);
    combine_kernel<<<dim3(2 * SCHUNKS, NA), 256>>>(x, out);
}

// round 16
// speedup vs baseline: 1.0240x; 1.0240x over previous
#include <cuda_runtime.h>
#include <math.h>

#define NV 3
#define NA 4
#define NN 50000
#define NC 128
#define NVA (NV * NA)

// Scratch; g_s zeroed each launch via memsetAsync.
__device__ __align__(16) float g_s[NVA * NC];
__device__ __align__(16) float g_u[NVA * NC];
__device__ float g_t[NVA];

#define SCHUNKS 98
#define SROWS   ((NN + SCHUNKS - 1) / SCHUNKS)   // 511

// -----------------------------------------------------------------------------
// Kernel 1: column sums (R13 exact: 50us, 78.5% DRAM, single wave 12x98).
// -----------------------------------------------------------------------------
__global__ __launch_bounds__(256) void col_sum_kernel(const float* __restrict__ x) {
    const int va = blockIdx.x;
    const int n0 = blockIdx.y * SROWS;
    const int n1 = min(n0 + SROWS, NN);

    const int lane = threadIdx.x & 31;
    const int w    = threadIdx.x >> 5;

    const float4* __restrict__ xb =
        reinterpret_cast<const float4*>(x) + (size_t)va * NN * 32;

    float4 acc = make_float4(0.f, 0.f, 0.f, 0.f);
    #pragma unroll 8
    for (int n = n0 + w; n < n1; n += 8) {
        float4 val = xb[(size_t)n * 32 + lane];
        acc.x += val.x; acc.y += val.y; acc.z += val.z; acc.w += val.w;
    }

    __shared__ float4 sm[256];
    sm[threadIdx.x] = acc;
    __syncthreads();

    if (threadIdx.x < 32) {
        float4 tot = sm[threadIdx.x];
        #pragma unroll
        for (int g = 1; g < 8; g++) {
            float4 val = sm[g * 32 + threadIdx.x];
            tot.x += val.x; tot.y += val.y; tot.z += val.z; tot.w += val.w;
        }
        float* dst = g_s + va * NC + threadIdx.x * 4;
        atomicAdd(dst + 0, tot.x);
        atomicAdd(dst + 1, tot.y);
        atomicAdd(dst + 2, tot.z);
        atomicAdd(dst + 3, tot.w);
    }
}

// -----------------------------------------------------------------------------
// Kernel 2 (tiny): u = (s/N)@W, t = (s/N).b. PDL: blocks pre-launch during
// col_sum drain; grid-dep sync before consuming g_s.
// -----------------------------------------------------------------------------
__global__ __launch_bounds__(128) void prep_kernel(const float* __restrict__ Wm,
                                                   const float* __restrict__ b) {
    cudaGridDependencySynchronize();

    const int va = blockIdx.x;
    const int q  = blockIdx.y;
    const int v  = va >> 2;
    const int cl = threadIdx.x & 31;
    const int dg = threadIdx.x >> 5;
    const int c  = q * 32 + cl;

    __shared__ float sh_s[NC];
    __shared__ float part[4][32];

    if (threadIdx.x < NC)
        sh_s[threadIdx.x] = g_s[va * NC + threadIdx.x] * (1.0f / (float)NN);
    __syncthreads();

    const float* __restrict__ Wv = Wm + (size_t)v * NC * NC;
    float acc = 0.f;
    #pragma unroll 8
    for (int d = dg * 32; d < dg * 32 + 32; ++d)
        acc += sh_s[d] * __ldg(&Wv[d * NC + c]);
    part[dg][cl] = acc;
    __syncthreads();

    if (dg == 0)
        g_u[va * NC + c] = (part[0][cl] + part[1][cl]) + (part[2][cl] + part[3][cl]);

    if (q == 0 && dg == 1) {
        const float* __restrict__ bv = b + v * NC;
        float tb = 0.f;
        #pragma unroll
        for (int d = cl; d < NC; d += 32) tb += sh_s[d] * bv[d];
        #pragma unroll
        for (int o = 16; o; o >>= 1) tb += __shfl_xor_sync(0xFFFFFFFFu, tb, o);
        if (cl == 0) g_t[va] = tb;
    }
}

// -----------------------------------------------------------------------------
// Kernel 3: scores -> tanh -> softmax over views -> combine (R13 math/ILP).
// PDL: blocks pre-launch during prep; iteration 0's six x-loads are issued
// BEFORE the grid-dep sync (x is independent of prep), hiding prep's runtime
// and the launch gap under the load ramp. grid (625,4), block 256.
// -----------------------------------------------------------------------------
__device__ __forceinline__ void combine_body(
    const float4 xa0, const float4 xa1, const float4 xa2,
    const float4 xb0, const float4 xb1, const float4 xb2,
    const float4 u0, const float4 u1, const float4 u2,
    const float t0, const float t1, const float t2,
    float4* __restrict__ oa_p, float4* __restrict__ ob_p)
{
    float pa0 = xa0.x * u0.x + xa0.y * u0.y + xa0.z * u0.z + xa0.w * u0.w;
    float pa1 = xa1.x * u1.x + xa1.y * u1.y + xa1.z * u1.z + xa1.w * u1.w;
    float pa2 = xa2.x * u2.x + xa2.y * u2.y + xa2.z * u2.z + xa2.w * u2.w;
    float pb0 = xb0.x * u0.x + xb0.y * u0.y + xb0.z * u0.z + xb0.w * u0.w;
    float pb1 = xb1.x * u1.x + xb1.y * u1.y + xb1.z * u1.z + xb1.w * u1.w;
    float pb2 = xb2.x * u2.x + xb2.y * u2.y + xb2.z * u2.z + xb2.w * u2.w;

    #pragma unroll
    for (int o = 16; o; o >>= 1) {
        pa0 += __shfl_xor_sync(0xFFFFFFFFu, pa0, o);
        pb0 += __shfl_xor_sync(0xFFFFFFFFu, pb0, o);
        pa1 += __shfl_xor_sync(0xFFFFFFFFu, pa1, o);
        pb1 += __shfl_xor_sync(0xFFFFFFFFu, pb1, o);
        pa2 += __shfl_xor_sync(0xFFFFFFFFu, pa2, o);
        pb2 += __shfl_xor_sync(0xFFFFFFFFu, pb2, o);
    }
    pa0 += t0; pa1 += t1; pa2 += t2;
    pb0 += t0; pb1 += t1; pb2 += t2;

    const float ea0 = __expf(__fdividef(2.f, 1.f + __expf(-2.f * pa0)) - 1.f);
    const float eb0 = __expf(__fdividef(2.f, 1.f + __expf(-2.f * pb0)) - 1.f);
    const float ea1 = __expf(__fdividef(2.f, 1.f + __expf(-2.f * pa1)) - 1.f);
    const float eb1 = __expf(__fdividef(2.f, 1.f + __expf(-2.f * pb1)) - 1.f);
    const float ea2 = __expf(__fdividef(2.f, 1.f + __expf(-2.f * pa2)) - 1.f);
    const float eb2 = __expf(__fdividef(2.f, 1.f + __expf(-2.f * pb2)) - 1.f);

    const float inva = __fdividef(1.f, ea0 + ea1 + ea2);
    const float invb = __fdividef(1.f, eb0 + eb1 + eb2);
    const float wa0 = ea0 * inva, wa1 = ea1 * inva, wa2 = ea2 * inva;
    const float wb0 = eb0 * invb, wb1 = eb1 * invb, wb2 = eb2 * invb;

    float4 oa, obv;
    oa.x = wa0 * xa0.x + wa1 * xa1.x + wa2 * xa2.x;
    oa.y = wa0 * xa0.y + wa1 * xa1.y + wa2 * xa2.y;
    oa.z = wa0 * xa0.z + wa1 * xa1.z + wa2 * xa2.z;
    oa.w = wa0 * xa0.w + wa1 * xa1.w + wa2 * xa2.w;
    obv.x = wb0 * xb0.x + wb1 * xb1.x + wb2 * xb2.x;
    obv.y = wb0 * xb0.y + wb1 * xb1.y + wb2 * xb2.y;
    obv.z = wb0 * xb0.z + wb1 * xb1.z + wb2 * xb2.z;
    obv.w = wb0 * xb0.w + wb1 * xb1.w + wb2 * xb2.w;
    __stcs(oa_p, oa);
    __stcs(ob_p, obv);
}

__global__ __launch_bounds__(256) void combine_kernel(const float* __restrict__ x,
                                                      float* __restrict__ out) {
    const int a    = blockIdx.y;
    const int lane = threadIdx.x & 31;
    const int warp = threadIdx.x >> 5;

    const size_t vstride = (size_t)NA * NN * 32;   // float4 units per view
    const float4* __restrict__ xb =
        reinterpret_cast<const float4*>(x) + (size_t)a * NN * 32;
    float4* __restrict__ ob =
        reinterpret_cast<float4*>(out) + (size_t)a * NN * 32;

    const int m = blockIdx.x * 8 + warp;           // 0..4999

    // Prefetch iteration 0 (independent of prep output), THEN grid-dep sync.
    const size_t ba0 = (size_t)m * 32 + lane;
    const size_t bb0 = (size_t)(m + 5000) * 32 + lane;
    const float4 pa_0 = xb[ba0];
    const float4 pb_0 = xb[bb0];
    const float4 pa_1 = xb[ba0 + vstride];
    const float4 pb_1 = xb[bb0 + vstride];
    const float4 pa_2 = xb[ba0 + 2 * vstride];
    const float4 pb_2 = xb[bb0 + 2 * vstride];

    cudaGridDependencySynchronize();

    const float4* ub = reinterpret_cast<const float4*>(g_u);
    const float4 u0 = ub[(size_t)(0 * NA + a) * 32 + lane];
    const float4 u1 = ub[(size_t)(1 * NA + a) * 32 + lane];
    const float4 u2 = ub[(size_t)(2 * NA + a) * 32 + lane];
    const float t0 = g_t[0 * NA + a];
    const float t1 = g_t[1 * NA + a];
    const float t2 = g_t[2 * NA + a];

    // Iteration 0 (prefetched)
    combine_body(pa_0, pa_1, pa_2, pb_0, pb_1, pb_2,
                 u0, u1, u2, t0, t1, t2, &ob[ba0], &ob[bb0]);

    // Iterations 1..4
    #pragma unroll
    for (int i = 1; i < 5; ++i) {
        const int na = m + i * 10000;
        const int nb = na + 5000;
        const size_t ba = (size_t)na * 32 + lane;
        const size_t bb = (size_t)nb * 32 + lane;

        const float4 xa0 = xb[ba];
        const float4 xb0 = xb[bb];
        const float4 xa1 = xb[ba + vstride];
        const float4 xb1 = xb[bb + vstride];
        const float4 xa2 = xb[ba + 2 * vstride];
        const float4 xb2 = xb[bb + 2 * vstride];

        combine_body(xa0, xa1, xa2, xb0, xb1, xb2,
                     u0, u1, u2, t0, t1, t2, &ob[ba], &ob[bb]);
    }
}

// -----------------------------------------------------------------------------
extern "C" void kernel_launch(void* const* d_in, const int* in_sizes, int n_in,
                              void* d_out, int out_size) {
    const float* x  = (const float*)d_in[0];   // [V,A,N,C]
    const float* Wm = (const float*)d_in[1];   // [V,C,C]
    const float* b  = (const float*)d_in[2];   // [V,C]
    float* out = (float*)d_out;                // [A,N,C]
    (void)in_sizes; (void)n_in; (void)out_size;

    void* p = nullptr;
    cudaGetSymbolAddress(&p, g_s);
    cudaMemsetAsync(p, 0, NVA * NC * sizeof(float));

    // Pass 1 (plain launch; ordered after memset by stream).
    col_sum_kernel<<<dim3(NVA, SCHUNKS), 256>>>(x);

    // prep + combine with programmatic (PDL) edges: blocks pre-launch during
    // the upstream kernel's drain; gridDependencySynchronize() inside each
    // kernel provides the actual data dependency.
    cudaLaunchAttribute attr[1];
    attr[0].id = cudaLaunchAttributeProgrammaticStreamSerialization;
    attr[0].val.programmaticStreamSerializationAllowed = 1;

    {
        cudaLaunchConfig_t cfg = {};
        cfg.gridDim  = dim3(NVA, 4);
        cfg.blockDim = dim3(128);
        cfg.stream   = 0;
        cfg.attrs    = attr;
        cfg.numAttrs = 1;
        cudaLaunchKernelEx(&cfg, prep_kernel, Wm, b);
    }
    {
        cudaLaunchConfig_t cfg = {};
        cfg.gridDim  = dim3(625, NA);
        cfg.blockDim = dim3(256);
        cfg.stream   = 0;
        cfg.attrs    = attr;
        cfg.numAttrs = 1;
        cudaLaunchKernelEx(&cfg, combine_kernel, x, out);
    }
}

// round 17
// speedup vs baseline: 1.0259x; 1.0019x over previous
#include <cuda_runtime.h>
#include <math.h>

#define NV 3
#define NA 4
#define NN 50000
#define NC 128
#define NVA (NV * NA)

// Scratch; g_s zeroed each launch via memsetAsync.
__device__ __align__(16) float g_s[NVA * NC];
__device__ __align__(16) float g_u[NVA * NC];
__device__ float g_t[NVA];

#define SCHUNKS 98
#define SROWS   ((NN + SCHUNKS - 1) / SCHUNKS)   // 511

// -----------------------------------------------------------------------------
// Kernel 1: column sums (R13 exact: 50us, 78.5% DRAM, single wave 12x98).
// -----------------------------------------------------------------------------
__global__ __launch_bounds__(256) void col_sum_kernel(const float* __restrict__ x) {
    const int va = blockIdx.x;
    const int n0 = blockIdx.y * SROWS;
    const int n1 = min(n0 + SROWS, NN);

    const int lane = threadIdx.x & 31;
    const int w    = threadIdx.x >> 5;

    const float4* __restrict__ xb =
        reinterpret_cast<const float4*>(x) + (size_t)va * NN * 32;

    float4 acc = make_float4(0.f, 0.f, 0.f, 0.f);
    #pragma unroll 8
    for (int n = n0 + w; n < n1; n += 8) {
        float4 val = xb[(size_t)n * 32 + lane];
        acc.x += val.x; acc.y += val.y; acc.z += val.z; acc.w += val.w;
    }

    __shared__ float4 sm[256];
    sm[threadIdx.x] = acc;
    __syncthreads();

    if (threadIdx.x < 32) {
        float4 tot = sm[threadIdx.x];
        #pragma unroll
        for (int g = 1; g < 8; g++) {
            float4 val = sm[g * 32 + threadIdx.x];
            tot.x += val.x; tot.y += val.y; tot.z += val.z; tot.w += val.w;
        }
        float* dst = g_s + va * NC + threadIdx.x * 4;
        atomicAdd(dst + 0, tot.x);
        atomicAdd(dst + 1, tot.y);
        atomicAdd(dst + 2, tot.z);
        atomicAdd(dst + 3, tot.w);
    }
}

// -----------------------------------------------------------------------------
// Kernel 2 (tiny): u = (s/N)@W, t = (s/N).b. PDL: blocks pre-launch during
// col_sum drain; grid-dep sync before consuming g_s.
// -----------------------------------------------------------------------------
__global__ __launch_bounds__(128) void prep_kernel(const float* __restrict__ Wm,
                                                   const float* __restrict__ b) {
    cudaGridDependencySynchronize();

    const int va = blockIdx.x;
    const int q  = blockIdx.y;
    const int v  = va >> 2;
    const int cl = threadIdx.x & 31;
    const int dg = threadIdx.x >> 5;
    const int c  = q * 32 + cl;

    __shared__ float sh_s[NC];
    __shared__ float part[4][32];

    if (threadIdx.x < NC)
        sh_s[threadIdx.x] = g_s[va * NC + threadIdx.x] * (1.0f / (float)NN);
    __syncthreads();

    const float* __restrict__ Wv = Wm + (size_t)v * NC * NC;
    float acc = 0.f;
    #pragma unroll 8
    for (int d = dg * 32; d < dg * 32 + 32; ++d)
        acc += sh_s[d] * __ldg(&Wv[d * NC + c]);
    part[dg][cl] = acc;
    __syncthreads();

    if (dg == 0)
        g_u[va * NC + c] = (part[0][cl] + part[1][cl]) + (part[2][cl] + part[3][cl]);

    if (q == 0 && dg == 1) {
        const float* __restrict__ bv = b + v * NC;
        float tb = 0.f;
        #pragma unroll
        for (int d = cl; d < NC; d += 32) tb += sh_s[d] * bv[d];
        #pragma unroll
        for (int o = 16; o; o >>= 1) tb += __shfl_xor_sync(0xFFFFFFFFu, tb, o);
        if (cl == 0) g_t[va] = tb;
    }
}

// -----------------------------------------------------------------------------
// Kernel 3: scores -> tanh -> softmax over views -> combine (R13 math/ILP).
// PDL: blocks pre-launch during prep; iteration 0's six x-loads are issued
// BEFORE the grid-dep sync (x is independent of prep), hiding prep's runtime
// and the launch gap under the load ramp. grid (625,4), block 256.
// -----------------------------------------------------------------------------
__device__ __forceinline__ void combine_body(
    const float4 xa0, const float4 xa1, const float4 xa2,
    const float4 xb0, const float4 xb1, const float4 xb2,
    const float4 u0, const float4 u1, const float4 u2,
    const float t0, const float t1, const float t2,
    float4* __restrict__ oa_p, float4* __restrict__ ob_p)
{
    float pa0 = xa0.x * u0.x + xa0.y * u0.y + xa0.z * u0.z + xa0.w * u0.w;
    float pa1 = xa1.x * u1.x + xa1.y * u1.y + xa1.z * u1.z + xa1.w * u1.w;
    float pa2 = xa2.x * u2.x + xa2.y * u2.y + xa2.z * u2.z + xa2.w * u2.w;
    float pb0 = xb0.x * u0.x + xb0.y * u0.y + xb0.z * u0.z + xb0.w * u0.w;
    float pb1 = xb1.x * u1.x + xb1.y * u1.y + xb1.z * u1.z + xb1.w * u1.w;
    float pb2 = xb2.x * u2.x + xb2.y * u2.y + xb2.z * u2.z + xb2.w * u2.w;

    #pragma unroll
    for (int o = 16; o; o >>= 1) {
        pa0 += __shfl_xor_sync(0xFFFFFFFFu, pa0, o);
        pb0 += __shfl_xor_sync(0xFFFFFFFFu, pb0, o);
        pa1 += __shfl_xor_sync(0xFFFFFFFFu, pa1, o);
        pb1 += __shfl_xor_sync(0xFFFFFFFFu, pb1, o);
        pa2 += __shfl_xor_sync(0xFFFFFFFFu, pa2, o);
        pb2 += __shfl_xor_sync(0xFFFFFFFFu, pb2, o);
    }
    pa0 += t0; pa1 += t1; pa2 += t2;
    pb0 += t0; pb1 += t1; pb2 += t2;

    const float ea0 = __expf(__fdividef(2.f, 1.f + __expf(-2.f * pa0)) - 1.f);
    const float eb0 = __expf(__fdividef(2.f, 1.f + __expf(-2.f * pb0)) - 1.f);
    const float ea1 = __expf(__fdividef(2.f, 1.f + __expf(-2.f * pa1)) - 1.f);
    const float eb1 = __expf(__fdividef(2.f, 1.f + __expf(-2.f * pb1)) - 1.f);
    const float ea2 = __expf(__fdividef(2.f, 1.f + __expf(-2.f * pa2)) - 1.f);
    const float eb2 = __expf(__fdividef(2.f, 1.f + __expf(-2.f * pb2)) - 1.f);

    const float inva = __fdividef(1.f, ea0 + ea1 + ea2);
    const float invb = __fdividef(1.f, eb0 + eb1 + eb2);
    const float wa0 = ea0 * inva, wa1 = ea1 * inva, wa2 = ea2 * inva;
    const float wb0 = eb0 * invb, wb1 = eb1 * invb, wb2 = eb2 * invb;

    float4 oa, obv;
    oa.x = wa0 * xa0.x + wa1 * xa1.x + wa2 * xa2.x;
    oa.y = wa0 * xa0.y + wa1 * xa1.y + wa2 * xa2.y;
    oa.z = wa0 * xa0.z + wa1 * xa1.z + wa2 * xa2.z;
    oa.w = wa0 * xa0.w + wa1 * xa1.w + wa2 * xa2.w;
    obv.x = wb0 * xb0.x + wb1 * xb1.x + wb2 * xb2.x;
    obv.y = wb0 * xb0.y + wb1 * xb1.y + wb2 * xb2.y;
    obv.z = wb0 * xb0.z + wb1 * xb1.z + wb2 * xb2.z;
    obv.w = wb0 * xb0.w + wb1 * xb1.w + wb2 * xb2.w;
    __stcs(oa_p, oa);
    __stcs(ob_p, obv);
}

__global__ __launch_bounds__(256) void combine_kernel(const float* __restrict__ x,
                                                      float* __restrict__ out) {
    const int a    = blockIdx.y;
    const int lane = threadIdx.x & 31;
    const int warp = threadIdx.x >> 5;

    const size_t vstride = (size_t)NA * NN * 32;   // float4 units per view
    const float4* __restrict__ xb =
        reinterpret_cast<const float4*>(x) + (size_t)a * NN * 32;
    float4* __restrict__ ob =
        reinterpret_cast<float4*>(out) + (size_t)a * NN * 32;

    const int m = blockIdx.x * 8 + warp;           // 0..4999

    // Prefetch iteration 0 (independent of prep output), THEN grid-dep sync.
    const size_t ba0 = (size_t)m * 32 + lane;
    const size_t bb0 = (size_t)(m + 5000) * 32 + lane;
    const float4 pa_0 = xb[ba0];
    const float4 pb_0 = xb[bb0];
    const float4 pa_1 = xb[ba0 + vstride];
    const float4 pb_1 = xb[bb0 + vstride];
    const float4 pa_2 = xb[ba0 + 2 * vstride];
    const float4 pb_2 = xb[bb0 + 2 * vstride];

    cudaGridDependencySynchronize();

    const float4* ub = reinterpret_cast<const float4*>(g_u);
    const float4 u0 = ub[(size_t)(0 * NA + a) * 32 + lane];
    const float4 u1 = ub[(size_t)(1 * NA + a) * 32 + lane];
    const float4 u2 = ub[(size_t)(2 * NA + a) * 32 + lane];
    const float t0 = g_t[0 * NA + a];
    const float t1 = g_t[1 * NA + a];
    const float t2 = g_t[2 * NA + a];

    // Iteration 0 (prefetched)
    combine_body(pa_0, pa_1, pa_2, pb_0, pb_1, pb_2,
                 u0, u1, u2, t0, t1, t2, &ob[ba0], &ob[bb0]);

    // Iterations 1..4
    #pragma unroll
    for (int i = 1; i < 5; ++i) {
        const int na = m + i * 10000;
        const int nb = na + 5000;
        const size_t ba = (size_t)na * 32 + lane;
        const size_t bb = (size_t)nb * 32 + lane;

        const float4 xa0 = xb[ba];
        const float4 xb0 = xb[bb];
        const float4 xa1 = xb[ba + vstride];
        const float4 xb1 = xb[bb + vstride];
        const float4 xa2 = xb[ba + 2 * vstride];
        const float4 xb2 = xb[bb + 2 * vstride];

        combine_body(xa0, xa1, xa2, xb0, xb1, xb2,
                     u0, u1, u2, t0, t1, t2, &ob[ba], &ob[bb]);
    }
}

// -----------------------------------------------------------------------------
extern "C" void kernel_launch(void* const* d_in, const int* in_sizes, int n_in,
                              void* d_out, int out_size) {
    const float* x  = (const float*)d_in[0];   // [V,A,N,C]
    const float* Wm = (const float*)d_in[1];   // [V,C,C]
    const float* b  = (const float*)d_in[2];   // [V,C]
    float* out = (float*)d_out;                // [A,N,C]
    (void)in_sizes; (void)n_in; (void)out_size;

    void* p = nullptr;
    cudaGetSymbolAddress(&p, g_s);
    cudaMemsetAsync(p, 0, NVA * NC * sizeof(float));

    // Pass 1 (plain launch; ordered after memset by stream).
    col_sum_kernel<<<dim3(NVA, SCHUNKS), 256>>>(x);

    // prep + combine with programmatic (PDL) edges: blocks pre-launch during
    // the upstream kernel's drain; gridDependencySynchronize() inside each
    // kernel provides the actual data dependency.
    cudaLaunchAttribute attr[1];
    attr[0].id = cudaLaunchAttributeProgrammaticStreamSerialization;
    attr[0].val.programmaticStreamSerializationAllowed = 1;

    {
        cudaLaunchConfig_t cfg = {};
        cfg.gridDim  = dim3(NVA, 4);
        cfg.blockDim = dim3(128);
        cfg.stream   = 0;
        cfg.attrs    = attr;
        cfg.numAttrs = 1;
        cudaLaunchKernelEx(&cfg, prep_kernel, Wm, b);
    }
    {
        cudaLaunchConfig_t cfg = {};
        cfg.gridDim  = dim3(625, NA);
        cfg.blockDim = dim3(256);
        cfg.stream   = 0;
        cfg.attrs    = attr;
        cfg.numAttrs = 1;
        cudaLaunchKernelEx(&cfg, combine_kernel, x, out);
    }
}